// round 2
// baseline (speedup 1.0000x reference)
#include <cuda_runtime.h>
#include <cuda_bf16.h>
#include <stdint.h>

// Problem constants (fixed by the dataset)
#define NMAX   100000
#define EMAX   1600000
#define D      128
#define SCANB  1024

// ---------------- device scratch (allocation-free rule: __device__ globals) ----
__device__ float g_z[NMAX * D];
__device__ float g_y[NMAX * D];
__device__ float g_h1[NMAX * D];
__device__ float g_h2[NMAX * D];
__device__ int   g_col[EMAX];
__device__ int   g_rowptr[NMAX + 1];
__device__ int   g_cursor[NMAX];
__device__ int   g_deg[NMAX];
__device__ float g_invdeg[NMAX];
__device__ int   g_bsums[1024];

// ---------------- CSR build ---------------------------------------------------
__global__ void zero_deg_kernel(int* deg, int n) {
    int i = blockIdx.x * blockDim.x + threadIdx.x;
    if (i < n) deg[i] = 0;
}

__global__ void hist_kernel(const int* __restrict__ dst, int* __restrict__ deg, int e) {
    int i = blockIdx.x * blockDim.x + threadIdx.x;
    if (i < e) atomicAdd(&deg[dst[i]], 1);
}

__global__ void invdeg_kernel(const int* __restrict__ deg, float* __restrict__ invdeg, int n) {
    int i = blockIdx.x * blockDim.x + threadIdx.x;
    if (i < n) {
        int d = deg[i];
        invdeg[i] = 1.0f / (float)(d > 0 ? d : 1);
    }
}

__global__ void scanA_kernel(const int* __restrict__ deg, int* __restrict__ excl,
                             int* __restrict__ bsums, int n) {
    __shared__ int sh[SCANB];
    int tid = threadIdx.x;
    int i = blockIdx.x * SCANB + tid;
    int v = (i < n) ? deg[i] : 0;
    sh[tid] = v;
    __syncthreads();
    for (int off = 1; off < SCANB; off <<= 1) {
        int t = (tid >= off) ? sh[tid - off] : 0;
        __syncthreads();
        sh[tid] += t;
        __syncthreads();
    }
    if (i < n) excl[i] = sh[tid] - v;      // exclusive within block
    if (tid == SCANB - 1) bsums[blockIdx.x] = sh[tid];
}

__global__ void scanB_kernel(int* __restrict__ bsums, int nb) {
    __shared__ int sh[1024];
    int tid = threadIdx.x;
    int v = (tid < nb) ? bsums[tid] : 0;
    sh[tid] = v;
    __syncthreads();
    for (int off = 1; off < 1024; off <<= 1) {
        int t = (tid >= off) ? sh[tid - off] : 0;
        __syncthreads();
        sh[tid] += t;
        __syncthreads();
    }
    if (tid < nb) bsums[tid] = sh[tid] - v;  // exclusive block offsets
}

__global__ void scanC_kernel(int* __restrict__ rowptr, int* __restrict__ cursor,
                             const int* __restrict__ bsums, int n, int e) {
    int i = blockIdx.x * blockDim.x + threadIdx.x;
    if (i < n) {
        int r = rowptr[i] + bsums[i >> 10];
        rowptr[i] = r;
        cursor[i] = r;
    }
    if (i == 0) rowptr[n] = e;
}

__global__ void scatter_kernel(const int* __restrict__ src,
                               const int* __restrict__ dst,
                               int* __restrict__ cursor, int* __restrict__ col, int e) {
    int i = blockIdx.x * blockDim.x + threadIdx.x;
    if (i < e) {
        int d = dst[i];
        int s = src[i];
        int pos = atomicAdd(&cursor[d], 1);
        col[pos] = s;
    }
}

// ---------------- transform: z = h @ Wl^T ; y = h @ Wr^T + b -------------------
// Block tile: 64 rows x 256 cols (cols 0..127 -> z, 128..255 -> y).
// 256 threads, thread micro-tile 8x8 (FMA-bound by design).
#define BM 64
#define KC 32

__global__ __launch_bounds__(256) void transform_kernel(
    const float* __restrict__ h,
    const float* __restrict__ Wl, const float* __restrict__ Wr,
    const float* __restrict__ bias,
    float* __restrict__ z, float* __restrict__ yo, int n)
{
    __shared__ float ws[KC][256];   // ws[k][j] = W_row_j[kb+k]   (j<128: Wl, else Wr)
    __shared__ float hs[BM][KC];    // hs[r][k] = h[row0+r][kb+k] (warp-broadcast reads)

    int tid = threadIdx.x;
    int tx = tid & 31;          // col group: cols tx*8 .. tx*8+7
    int ty = tid >> 5;          // row group: rows ty*8 .. ty*8+7
    int row0 = blockIdx.x * BM;
    int ty8 = ty * 8;
    int cb = tx * 8;

    float acc[8][8];
#pragma unroll
    for (int r = 0; r < 8; r++)
#pragma unroll
        for (int c = 0; c < 8; c++) acc[r][c] = 0.0f;

    for (int kb = 0; kb < D; kb += KC) {
        // load W chunk (transposed into ws)
        {
            int j = tid;  // 0..255
            const float* srcw = (j < 128) ? (Wl + j * D + kb) : (Wr + (j - 128) * D + kb);
#pragma unroll
            for (int q = 0; q < 8; q++) {
                float4 v = *(const float4*)(srcw + q * 4);
                ws[q * 4 + 0][j] = v.x;
                ws[q * 4 + 1][j] = v.y;
                ws[q * 4 + 2][j] = v.z;
                ws[q * 4 + 3][j] = v.w;
            }
        }
        // load h chunk: 64 rows x 32 floats = 512 float4, 2 per thread
#pragma unroll
        for (int p = 0; p < 2; p++) {
            int id = tid + p * 256;
            int r = id >> 3;
            int slot = id & 7;
            int grow = row0 + r;
            float4 v = make_float4(0.f, 0.f, 0.f, 0.f);
            if (grow < n) v = *(const float4*)(h + (size_t)grow * D + kb + slot * 4);
            *(float4*)(&hs[r][slot * 4]) = v;
        }
        __syncthreads();

#pragma unroll
        for (int k = 0; k < KC; k++) {
            float4 w0 = *(const float4*)(&ws[k][cb]);
            float4 w1 = *(const float4*)(&ws[k][cb + 4]);
            float wv[8] = {w0.x, w0.y, w0.z, w0.w, w1.x, w1.y, w1.z, w1.w};
#pragma unroll
            for (int r = 0; r < 8; r++) {
                float hv = hs[ty8 + r][k];   // uniform within warp -> broadcast
#pragma unroll
                for (int c = 0; c < 8; c++) acc[r][c] = fmaf(hv, wv[c], acc[r][c]);
            }
        }
        __syncthreads();
    }

    // epilogue
    if (cb < 128) {
#pragma unroll
        for (int r = 0; r < 8; r++) {
            int grow = row0 + ty8 + r;
            if (grow < n) {
                float4 a0 = make_float4(acc[r][0], acc[r][1], acc[r][2], acc[r][3]);
                float4 a1 = make_float4(acc[r][4], acc[r][5], acc[r][6], acc[r][7]);
                *(float4*)(z + (size_t)grow * D + cb) = a0;
                *(float4*)(z + (size_t)grow * D + cb + 4) = a1;
            }
        }
    } else {
        int c0 = cb - 128;
        float bv[8];
#pragma unroll
        for (int c = 0; c < 8; c++) bv[c] = bias[c0 + c];
#pragma unroll
        for (int r = 0; r < 8; r++) {
            int grow = row0 + ty8 + r;
            if (grow < n) {
                float4 a0 = make_float4(acc[r][0] + bv[0], acc[r][1] + bv[1],
                                        acc[r][2] + bv[2], acc[r][3] + bv[3]);
                float4 a1 = make_float4(acc[r][4] + bv[4], acc[r][5] + bv[5],
                                        acc[r][6] + bv[6], acc[r][7] + bv[7]);
                *(float4*)(yo + (size_t)grow * D + c0) = a0;
                *(float4*)(yo + (size_t)grow * D + c0 + 4) = a1;
            }
        }
    }
}

// ---------------- aggregation: out[i] = act(sum z[col] * invdeg + y) -----------
// One warp per node; each lane owns 4 contiguous floats (float4) of the row.
__global__ __launch_bounds__(256) void aggregate_kernel(
    const float* __restrict__ z, const float* __restrict__ y,
    const int* __restrict__ rowptr, const int* __restrict__ col,
    const float* __restrict__ invdeg, float* __restrict__ out,
    int n, int do_relu)
{
    int warp = (int)((blockIdx.x * blockDim.x + threadIdx.x) >> 5);
    int lane = threadIdx.x & 31;
    if (warp >= n) return;

    int beg = rowptr[warp];
    int end = rowptr[warp + 1];

    float4 acc = make_float4(0.f, 0.f, 0.f, 0.f);
    for (int e = beg; e < end; e++) {
        int s = __ldg(&col[e]);
        float4 v = *(const float4*)(z + (size_t)s * D + lane * 4);
        acc.x += v.x; acc.y += v.y; acc.z += v.z; acc.w += v.w;
    }
    float inv = invdeg[warp];
    float4 yv = *(const float4*)(y + (size_t)warp * D + lane * 4);
    float4 o;
    o.x = fmaf(acc.x, inv, yv.x);
    o.y = fmaf(acc.y, inv, yv.y);
    o.z = fmaf(acc.z, inv, yv.z);
    o.w = fmaf(acc.w, inv, yv.w);
    if (do_relu) {
        o.x = fmaxf(o.x, 0.f); o.y = fmaxf(o.y, 0.f);
        o.z = fmaxf(o.z, 0.f); o.w = fmaxf(o.w, 0.f);
    }
    *(float4*)(out + (size_t)warp * D + lane * 4) = o;
}

// ---------------- launch -------------------------------------------------------
extern "C" void kernel_launch(void* const* d_in, const int* in_sizes, int n_in,
                              void* d_out, int out_size) {
    const float* x  = (const float*)d_in[0];
    const int*   ei = (const int*)d_in[1];      // int32! (JAX downcasts int64 without x64)
    const float* Wl[3] = {(const float*)d_in[2], (const float*)d_in[5], (const float*)d_in[8]};
    const float* Wr[3] = {(const float*)d_in[3], (const float*)d_in[6], (const float*)d_in[9]};
    const float* bb[3] = {(const float*)d_in[4], (const float*)d_in[7], (const float*)d_in[10]};
    float* out = (float*)d_out;

    int n = in_sizes[0] / D;        // 100000
    int e = in_sizes[1] / 2;        // 1600000
    const int* src = ei;
    const int* dst = ei + e;

    // scratch pointers via symbol lookup (no allocation)
    float *p_z, *p_y, *p_h1, *p_h2, *p_invdeg;
    int *p_col, *p_rowptr, *p_cursor, *p_deg, *p_bsums;
    cudaGetSymbolAddress((void**)&p_z,      g_z);
    cudaGetSymbolAddress((void**)&p_y,      g_y);
    cudaGetSymbolAddress((void**)&p_h1,     g_h1);
    cudaGetSymbolAddress((void**)&p_h2,     g_h2);
    cudaGetSymbolAddress((void**)&p_invdeg, g_invdeg);
    cudaGetSymbolAddress((void**)&p_col,    g_col);
    cudaGetSymbolAddress((void**)&p_rowptr, g_rowptr);
    cudaGetSymbolAddress((void**)&p_cursor, g_cursor);
    cudaGetSymbolAddress((void**)&p_deg,    g_deg);
    cudaGetSymbolAddress((void**)&p_bsums,  g_bsums);

    int nb_n = (n + 255) / 256;
    int nb_e = (e + 255) / 256;
    int nb_scan = (n + SCANB - 1) / SCANB;

    // ---- CSR build (once per launch) ----
    zero_deg_kernel<<<nb_n, 256>>>(p_deg, n);
    hist_kernel<<<nb_e, 256>>>(dst, p_deg, e);
    invdeg_kernel<<<nb_n, 256>>>(p_deg, p_invdeg, n);
    scanA_kernel<<<nb_scan, SCANB>>>(p_deg, p_rowptr, p_bsums, n);
    scanB_kernel<<<1, 1024>>>(p_bsums, nb_scan);
    scanC_kernel<<<nb_n, 256>>>(p_rowptr, p_cursor, p_bsums, n, e);
    scatter_kernel<<<nb_e, 256>>>(src, dst, p_cursor, p_col, e);

    // ---- 3 layers: transform then aggregate ----
    int nb_tr = (n + BM - 1) / BM;                 // 1563
    int nb_ag = (n * 32 + 255) / 256;              // warp per node

    const float* hin = x;
    float* houts[3] = {p_h1, p_h2, out};
    for (int l = 0; l < 3; l++) {
        transform_kernel<<<nb_tr, 256>>>(hin, Wl[l], Wr[l], bb[l], p_z, p_y, n);
        aggregate_kernel<<<nb_ag, 256>>>(p_z, p_y, p_rowptr, p_col, p_invdeg,
                                         houts[l], n, (l < 2) ? 1 : 0);
        hin = houts[l];
    }
}